// round 14
// baseline (speedup 1.0000x reference)
#include <cuda_runtime.h>
#include <cstdint>

#define NF 27
#define FD 128
#define NPAIRS 351
#define OUT_STRIDE (NF*FD + NPAIRS)   // 3807 (odd -> out rows only 4B-aligned)
#define ROWPAD 144                     // 128B payload + 16B pad: frag LDS conflict-free
#define BUFB (32 * ROWPAD)             // 4608 B per chunk buffer (rows 27-31 stay zero)
#define WARPB (2 * BUFB)               // 9216 B per warp; 4 warps = 36864 B static smem

__device__ __forceinline__ uint32_t smem_u32(const void* p) {
    uint32_t a;
    asm("{ .reg .u64 t; cvta.to.shared.u64 t, %1; cvt.u32.u64 %0, t; }" : "=r"(a) : "l"(p));
    return a;
}

#define CP_ASYNC16(saddr, gptr) \
    asm volatile("cp.async.cg.shared.global [%0], [%1], 16;" \
                 :: "r"(saddr), "l"(gptr) : "memory")
#define CP_COMMIT()  asm volatile("cp.async.commit_group;" ::: "memory")
#define CP_WAIT(n)   asm volatile("cp.async.wait_group %0;" :: "n"(n) : "memory")

#define CVT_TF32(d, f) asm("cvt.rna.tf32.f32 %0, %1;" : "=r"(d) : "f"(f))

#define LDS32(d, addr) \
    asm volatile("ld.shared.b32 %0, [%1];" : "=r"(d) : "r"(addr))

#define MMA_T(accv, a0, a1, a2, a3, b0, b1) \
    asm volatile("mma.sync.aligned.m16n8k8.row.col.f32.tf32.tf32.f32 " \
                 "{%0,%1,%2,%3}, {%4,%5,%6,%7}, {%8,%9}, {%0,%1,%2,%3};" \
                 : "+f"((accv)[0]), "+f"((accv)[1]), "+f"((accv)[2]), "+f"((accv)[3]) \
                 : "r"(a0), "r"(a1), "r"(a2), "r"(a3), "r"(b0), "r"(b1))

// Warp-per-batch Gram via single-pass tf32 mma.sync (rna-rounded), fragments
// loaded directly from the padded cp.async fp32 buffer (no bf16 tiles, no
// ldmatrix). 6-tile upper-triangle cover, double-buffered chunk pipeline.
__global__ void __launch_bounds__(128, 6)
fi_kernel(const float* __restrict__ in, float* __restrict__ out)
{
    __shared__ __align__(16) char smem[4 * WARPB];

    const int w    = threadIdx.x >> 5;
    const int lane = threadIdx.x & 31;
    const long b   = (long)blockIdx.x * 4 + w;

    const char* __restrict__ ebc =
        reinterpret_cast<const char*>(in) + b * (long)(NF * FD) * 4;
    float* __restrict__ ob = out + b * (long)OUT_STRIDE;

    char* buf0 = smem + w * WARPB;
    char* buf1 = buf0 + BUFB;
    const uint32_t ba[2] = { smem_u32(buf0), smem_u32(buf1) };

    // zero rows 27..31 of both buffers once (cp.async never writes them)
    for (int idx = lane; idx < (5 * ROWPAD) / 4; idx += 32) {
        reinterpret_cast<uint32_t*>(buf0 + 27 * ROWPAD)[idx] = 0;
        reinterpret_cast<uint32_t*>(buf1 + 27 * ROWPAD)[idx] = 0;
    }

    // 6 tiles: t0..t3 = (m0,g0..g3), t4 = (m1,g2), t5 = (m1,g3)
    float acc[6][4];
#pragma unroll
    for (int t = 0; t < 6; t++)
#pragma unroll
        for (int e = 0; e < 4; e++) acc[t][e] = 0.0f;

    const int half = lane >> 4;
    const int ks   = lane & 15;

    // one 27x32-float chunk = 216 16B segments
    auto issue_chunk = [&](uint32_t fbuf, int kc) {
#pragma unroll
        for (int it = 0; it < 7; it++) {
            const int idx = it * 32 + lane;          // 0..223
            if (idx < NF * 8) {
                const int f = idx >> 3, seg = idx & 7;
                CP_ASYNC16(fbuf + (uint32_t)(f * ROWPAD + seg * 16),
                           ebc + f * 512 + kc * 4 + seg * 16);
            }
        }
        CP_COMMIT();
    };

    issue_chunk(ba[0], 0);
    issue_chunk(ba[1], 32);

    // fragment base addresses (invariant parts)
    const uint32_t fr_row = (uint32_t)((lane >> 2) * ROWPAD + (lane & 3) * 4);

#pragma unroll
    for (int c = 0; c < 4; c++) {
        const int kc = c * 32;
        if (c < 3) { CP_WAIT(1); } else { CP_WAIT(0); }
        __syncwarp();

        const uint32_t bb = ba[c & 1];
        char* bc = (c & 1) ? buf1 : buf0;

        // ---- copy-out (exact fp32) + in-place tf32 rounding ----
#pragma unroll
        for (int it = 0; it < 14; it++) {
            const int f = 2 * it + half;
            if (f < NF) {
                float2 v = *reinterpret_cast<const float2*>(bc + f * ROWPAD + ks * 8);
                ob[f * FD + kc + 2 * ks]     = v.x;   // rows 4B-aligned: scalar
                ob[f * FD + kc + 2 * ks + 1] = v.y;
                uint2 r;
                CVT_TF32(r.x, v.x);
                CVT_TF32(r.y, v.y);
                *reinterpret_cast<uint2*>(bc + f * ROWPAD + ks * 8) = r;
            }
        }
        __syncwarp();

        // ---- MMA: 4 k8 units, 8 LDS.32 + 6 tf32 MMAs each ----
#pragma unroll
        for (int kk = 0; kk < 4; kk++) {
            const uint32_t base = bb + fr_row + (uint32_t)(kk * 32);
            uint32_t a0, a1, a2, a3, c0, c1, c2, c3;
            LDS32(a0, base);                        // (r,      k)
            LDS32(a1, base + 8 * ROWPAD);           // (r+8,    k)
            LDS32(a2, base + 16);                   // (r,      k+4)
            LDS32(a3, base + 8 * ROWPAD + 16);      // (r+8,    k+4)
            LDS32(c0, base + 16 * ROWPAD);          // (r+16,   k)
            LDS32(c1, base + 24 * ROWPAD);          // (r+24,   k)
            LDS32(c2, base + 16 * ROWPAD + 16);     // (r+16,   k+4)
            LDS32(c3, base + 24 * ROWPAD + 16);     // (r+24,   k+4)

            MMA_T(acc[0], a0, a1, a2, a3, a0, a2);  // (m0, g0)
            MMA_T(acc[1], a0, a1, a2, a3, a1, a3);  // (m0, g1)
            MMA_T(acc[2], a0, a1, a2, a3, c0, c2);  // (m0, g2)
            MMA_T(acc[3], a0, a1, a2, a3, c1, c3);  // (m0, g3)
            MMA_T(acc[4], c0, c1, c2, c3, c0, c2);  // (m1, g2)
            MMA_T(acc[5], c0, c1, c2, c3, c1, c3);  // (m1, g3)
        }
        __syncwarp();   // buffer may now be refilled

        // ---- refill this buffer with chunk c+2 ----
        if (c < 2) issue_chunk(bb, kc + 64);
    }

    // ---- epilogue: scatter triu dots into smem stage, coalesced copy-out ----
    float* stage = reinterpret_cast<float*>(buf0);
    {
        const int r4 = lane >> 2;
        const int c2 = 2 * (lane & 3);
        const int tm[6] = {0, 0, 0, 0, 1, 1};
        const int tg[6] = {0, 1, 2, 3, 2, 3};
#pragma unroll
        for (int t = 0; t < 6; t++) {
#pragma unroll
            for (int e = 0; e < 4; e++) {
                const int i = 16 * tm[t] + r4 + ((e >= 2) ? 8 : 0);
                const int j = 8 * tg[t] + c2 + (e & 1);
                if (j > i && j < NF) {
                    stage[(i * (53 - i)) / 2 + (j - i - 1)] = acc[t][e];
                }
            }
        }
    }
    __syncwarp();

    float* oint = ob + NF * FD;
#pragma unroll
    for (int t = 0; t < 11; t++) {
        const int idx = t * 32 + lane;
        if (idx < NPAIRS) oint[idx] = stage[idx];
    }
}

extern "C" void kernel_launch(void* const* d_in, const int* in_sizes, int n_in,
                              void* d_out, int out_size)
{
    const float* in = (const float*)d_in[0];
    float* out = (float*)d_out;
    const int B = in_sizes[0] / (NF * FD);   // 16384
    fi_kernel<<<B / 4, 128>>>(in, out);
}